// round 14
// baseline (speedup 1.0000x reference)
#include <cuda_runtime.h>
#include <cuda_fp16.h>
#include <math.h>
#include <stdint.h>

// ---------------------------------------------------------------------------
// Problem dims (fixed for this dataset)
// ---------------------------------------------------------------------------
#define BDIM 256
#define DDIM 2048
#define HDIM 4096
#define MAX_STEPS 64

#define BK 32
#define THREADS 256
#define NSTAGE 4
#define ROWB 80          // 32 fp16 (64B) + 16B pad -> conflict-free LDSM

// ---------------------------------------------------------------------------
// Device scratch (no cudaMalloc allowed)
// ---------------------------------------------------------------------------
__device__ __half g_W1T[(size_t)HDIM * DDIM];   // [N=4096][K=2048] fp16
__device__ __half g_W2T[(size_t)DDIM * HDIM];   // [N=2048][K=4096] fp16
__device__ __half g_z_h[(size_t)BDIM * DDIM];
__device__ __half g_h1_h[(size_t)BDIM * HDIM];
__device__ float g_sched_t[MAX_STEPS];
__device__ float g_sched_h[MAX_STEPS];
__device__ int   g_nsteps;

// ---------------------------------------------------------------------------
// PTX helpers (compute_103-portable: cp.async, ldmatrix, mma.sync)
// ---------------------------------------------------------------------------
__device__ __forceinline__ uint32_t smem_to_u32(const void* p) {
    uint32_t a;
    asm("{ .reg .u64 t; cvta.to.shared.u64 t, %1; cvt.u32.u64 %0, t; }"
        : "=r"(a) : "l"(p));
    return a;
}

__device__ __forceinline__ void cp_async16(uint32_t dst, const void* src) {
    asm volatile("cp.async.cg.shared.global [%0], [%1], 16;"
                 :: "r"(dst), "l"(src));
}
#define CP_COMMIT() asm volatile("cp.async.commit_group;" ::: "memory")
#define CP_WAIT2()  asm volatile("cp.async.wait_group 2;" ::: "memory")

__device__ __forceinline__ void ldsm_x4(uint32_t& r0, uint32_t& r1,
                                        uint32_t& r2, uint32_t& r3,
                                        uint32_t addr) {
    asm volatile("ldmatrix.sync.aligned.m8n8.x4.shared.b16 {%0,%1,%2,%3}, [%4];"
                 : "=r"(r0), "=r"(r1), "=r"(r2), "=r"(r3) : "r"(addr));
}

__device__ __forceinline__ void mma_f16(float* c, const uint32_t* a,
                                        const uint32_t* b) {
    asm volatile(
        "mma.sync.aligned.m16n8k16.row.col.f32.f16.f16.f32 "
        "{%0,%1,%2,%3}, {%4,%5,%6,%7}, {%8,%9}, {%0,%1,%2,%3};"
        : "+f"(c[0]), "+f"(c[1]), "+f"(c[2]), "+f"(c[3])
        : "r"(a[0]), "r"(a[1]), "r"(a[2]), "r"(a[3]), "r"(b[0]), "r"(b[1]));
}

// Hardware tanh (MUFU.TANH, sm_75+): 1 instruction vs ~20 for tanhf.
__device__ __forceinline__ float tanh_approx(float x) {
    float y;
    asm("tanh.approx.f32 %0, %1;" : "=f"(y) : "f"(x));
    return y;
}

// ---------------------------------------------------------------------------
// Schedule: exact replica of the reference's host-side step scheduling
// ---------------------------------------------------------------------------
__global__ void schedule_kernel(const float* __restrict__ t, int T) {
    if (threadIdx.x != 0 || blockIdx.x != 0) return;
    int s = 0;
    for (int i = 0; i < T - 1; i++) {
        double t0 = (double)t[i];
        double t1 = (double)t[i + 1];
        double d  = fabs(t1 - t0);
        int n = (int)ceil(d / 0.05);
        if (n < 1) n = 1;
        float h = (float)((t1 - t0) / (double)n);
        float tc = t[i];
        for (int k = 0; k < n && s < MAX_STEPS; k++) {
            tc = tc + h;                 // t += h BEFORE f eval
            g_sched_t[s] = tc;
            g_sched_h[s] = h;
            s++;
        }
    }
    g_nsteps = s;
}

// ---------------------------------------------------------------------------
// Weight transpose + fp16 convert:  W[K][N] fp32 -> WT[N][K] fp16
// ---------------------------------------------------------------------------
__global__ void transpose_convert_kernel(const float* __restrict__ W,
                                         int K, int N, int which) {
    __shared__ float tile[32][33];
    const int k0 = blockIdx.y * 32;
    const int n0 = blockIdx.x * 32;
    const int tx = threadIdx.x % 32;
    const int ty = threadIdx.x / 32;

    #pragma unroll
    for (int i = 0; i < 32; i += 8)
        tile[ty + i][tx] = W[(size_t)(k0 + ty + i) * N + n0 + tx];
    __syncthreads();

    __half* T = which ? g_W2T : g_W1T;
    #pragma unroll
    for (int i = 0; i < 32; i += 8) {
        float v = tile[tx][ty + i];
        T[(size_t)(n0 + ty + i) * K + k0 + tx] = __float2half_rn(v);
    }
}

__global__ void zinit_kernel(const float* __restrict__ z0, float* __restrict__ z) {
    int i = blockIdx.x * blockDim.x + threadIdx.x;
    if (i >= BDIM * DDIM) return;
    float v = z0[i];
    z[i] = v;
    g_z_h[i] = __float2half_rn(v);
}

// ---------------------------------------------------------------------------
// Unified pipelined fp16 GEMM, 256 threads (8 warps). R12 configuration,
// both GEMMs now on 64x64 tiles -> 256-CTA grid for gemmA (occupancy 2:
// two CTAs co-resident per SM -> 4 warps/SMSP, barrier gates only one CTA).
//   MODE 0: h1 = tanh( z @ W1 + b1 + t*u )   A=g_z_h,  B=g_W1T, K=DDIM
//   MODE 1: z += h * ( h1 @ W2 + b2 )        A=g_h1_h, B=g_W2T, K=HDIM
// ---------------------------------------------------------------------------
template<int BMT, int BNT, int MODE>
__global__ void __launch_bounds__(THREADS, 2)
gemm_kernel(const float* __restrict__ bias, const float* __restrict__ uvec,
            float* __restrict__ z, int step)
{
    if (step >= g_nsteps) return;

    constexpr int WARPS_M = BMT / 32;
    constexpr int WARPS_N = 8 / WARPS_M;
    constexpr int WN = BNT / WARPS_N;      // warp tile N
    constexpr int NT = WN / 8;             // n8 frags per warp
    constexpr int KDIM = MODE ? HDIM : DDIM;
    constexpr int RTOT = BMT + BNT;
    constexpr int ST_B = BMT * ROWB;
    constexpr int STAGE = RTOT * ROWB;
    constexpr int NLOAD = RTOT * 4 / THREADS;

    extern __shared__ char smem[];
    const uint32_t sbase = smem_to_u32(smem);
    const int tid = threadIdx.x;
    const int wid = tid >> 5, lane = tid & 31;
    const int warp_m = wid % WARPS_M;
    const int warp_n = wid / WARPS_M;
    const int m0 = blockIdx.y * BMT;
    const int n0 = blockIdx.x * BNT;

    const __half* __restrict__ A  = (MODE ? g_h1_h : g_z_h) + (size_t)m0 * KDIM;
    const __half* __restrict__ Bw = (MODE ? g_W2T  : g_W1T) + (size_t)n0 * KDIM;

    float acc[2][NT][4];
    #pragma unroll
    for (int mt = 0; mt < 2; mt++)
        #pragma unroll
        for (int nt = 0; nt < NT; nt++)
            #pragma unroll
            for (int q = 0; q < 4; q++) acc[mt][nt][q] = 0.0f;

    // --- stage loader ---
    auto load_stage = [&](uint32_t dstbase, int ko) {
        #pragma unroll
        for (int o = 0; o < NLOAD; o++) {
            int id = tid + THREADS * o;
            int row = id >> 2, ch = id & 3;
            const __half* src = (row < BMT)
                ? A  + (size_t)row * KDIM + ko + ch * 8
                : Bw + (size_t)(row - BMT) * KDIM + ko + ch * 8;
            cp_async16(dstbase + row * ROWB + ch * 16, src);
        }
    };

    // --- per-stage compute ---
    auto compute_stage = [&](uint32_t st) {
        #pragma unroll
        for (int kk = 0; kk < 2; kk++) {
            uint32_t a[2][4];
            #pragma unroll
            for (int mt = 0; mt < 2; mt++) {
                uint32_t off = (uint32_t)((warp_m * 32 + mt * 16 + (lane & 15)) * ROWB
                                          + kk * 32 + ((lane >> 4) << 4));
                ldsm_x4(a[mt][0], a[mt][1], a[mt][2], a[mt][3], st + off);
            }
            uint32_t b[NT][2];
            #pragma unroll
            for (int pr = 0; pr < NT / 2; pr++) {
                uint32_t off = (uint32_t)(ST_B
                    + (warp_n * WN + pr * 16 + ((lane & 16) >> 1) + (lane & 7)) * ROWB
                    + kk * 32 + ((lane & 8) << 1));
                uint32_t r0, r1, r2, r3;
                ldsm_x4(r0, r1, r2, r3, st + off);
                b[2 * pr][0] = r0; b[2 * pr][1] = r1;
                b[2 * pr + 1][0] = r2; b[2 * pr + 1][1] = r3;
            }
            #pragma unroll
            for (int mt = 0; mt < 2; mt++)
                #pragma unroll
                for (int nt = 0; nt < NT; nt++)
                    mma_f16(acc[mt][nt], a[mt], b[nt]);
        }
    };

    // --- 4-stage pipeline ---
    const int nIter = KDIM / BK;
    load_stage(sbase + 0 * STAGE, 0);      CP_COMMIT();
    load_stage(sbase + 1 * STAGE, BK);     CP_COMMIT();
    load_stage(sbase + 2 * STAGE, 2 * BK); CP_COMMIT();

    int stg = 0;
    for (int it = 0; it < nIter; it++) {
        CP_WAIT2();
        __syncthreads();
        compute_stage(sbase + stg * STAGE);
        int pf = it + 3;
        if (pf < nIter) {
            int ps = stg + 3; if (ps >= NSTAGE) ps -= NSTAGE;
            load_stage(sbase + ps * STAGE, pf * BK);
        }
        CP_COMMIT();
        stg++; if (stg == NSTAGE) stg = 0;
    }

    // --- epilogue ---
    const int grp = lane >> 2, qid = lane & 3;

    if (MODE == 0) {
        const float tb = g_sched_t[step];
        #pragma unroll
        for (int mt = 0; mt < 2; mt++) {
            #pragma unroll
            for (int nt = 0; nt < NT; nt++) {
                const int m = m0 + warp_m * 32 + mt * 16 + grp;
                const int n = n0 + warp_n * WN + nt * 8 + 2 * qid;
                const float bias0 = __ldg(&bias[n])     + tb * __ldg(&uvec[n]);
                const float bias1 = __ldg(&bias[n + 1]) + tb * __ldg(&uvec[n + 1]);
                #pragma unroll
                for (int half = 0; half < 2; half++) {
                    const int mm = m + 8 * half;
                    float y0 = tanh_approx(acc[mt][nt][2 * half + 0] + bias0);
                    float y1 = tanh_approx(acc[mt][nt][2 * half + 1] + bias1);
                    __half2 hv;
                    hv.x = __float2half_rn(y0);
                    hv.y = __float2half_rn(y1);
                    *(__half2*)&g_h1_h[(size_t)mm * HDIM + n] = hv;
                }
            }
        }
    } else {
        const float h = g_sched_h[step];
        #pragma unroll
        for (int mt = 0; mt < 2; mt++) {
            #pragma unroll
            for (int nt = 0; nt < NT; nt++) {
                const int m = m0 + warp_m * 32 + mt * 16 + grp;
                const int n = n0 + warp_n * WN + nt * 8 + 2 * qid;
                const float bias0 = __ldg(&bias[n]);
                const float bias1 = __ldg(&bias[n + 1]);
                #pragma unroll
                for (int half = 0; half < 2; half++) {
                    const int mm = m + 8 * half;
                    const size_t idx = (size_t)mm * DDIM + n;
                    float2 zv = *(float2*)&z[idx];
                    zv.x += h * (acc[mt][nt][2 * half + 0] + bias0);
                    zv.y += h * (acc[mt][nt][2 * half + 1] + bias1);
                    *(float2*)&z[idx] = zv;
                    __half2 hv;
                    hv.x = __float2half_rn(zv.x);
                    hv.y = __float2half_rn(zv.y);
                    *(__half2*)&g_z_h[idx] = hv;
                }
            }
        }
    }
}

// ---------------------------------------------------------------------------
// Launch
// ---------------------------------------------------------------------------
#define SMEM_AB ((64 + 64) * ROWB * NSTAGE)   // 40960 (both GEMMs, 64x64 tiles)

extern "C" void kernel_launch(void* const* d_in, const int* in_sizes, int n_in,
                              void* d_out, int out_size)
{
    const float* z0 = (const float*)d_in[0];
    const float* t  = (const float*)d_in[1];
    const float* W1 = (const float*)d_in[2];
    const float* b1 = (const float*)d_in[3];
    const float* u  = (const float*)d_in[4];
    const float* W2 = (const float*)d_in[5];
    const float* b2 = (const float*)d_in[6];
    float* z = (float*)d_out;

    const int T = in_sizes[1];

    cudaFuncSetAttribute((const void*)gemm_kernel<64, 64, 0>,
        cudaFuncAttributeMaxDynamicSharedMemorySize, SMEM_AB);
    cudaFuncSetAttribute((const void*)gemm_kernel<64, 64, 1>,
        cudaFuncAttributeMaxDynamicSharedMemorySize, SMEM_AB);

    schedule_kernel<<<1, 32>>>(t, T);
    transpose_convert_kernel<<<dim3(HDIM / 32, DDIM / 32), 256>>>(W1, DDIM, HDIM, 0);
    transpose_convert_kernel<<<dim3(DDIM / 32, HDIM / 32), 256>>>(W2, HDIM, DDIM, 1);
    zinit_kernel<<<(BDIM * DDIM + 255) / 256, 256>>>(z0, z);

    int max_launch = 3 * (T - 1);
    if (max_launch > MAX_STEPS) max_launch = MAX_STEPS;

    const dim3 blk(THREADS);
    const dim3 gridA(HDIM / 64, BDIM / 64);    // 64 x 4 = 256 CTAs (occ 2)
    const dim3 gridB(DDIM / 64, BDIM / 64);    // 32 x 4 = 128 CTAs

    for (int s = 0; s < max_launch; s++) {
        gemm_kernel<64, 64, 0><<<gridA, blk, SMEM_AB>>>(b1, u, z, s);
        gemm_kernel<64, 64, 1><<<gridB, blk, SMEM_AB>>>(b2, nullptr, z, s);
    }
}

// round 15
// speedup vs baseline: 1.0952x; 1.0952x over previous
#include <cuda_runtime.h>
#include <cuda_fp16.h>
#include <math.h>
#include <stdint.h>

// ---------------------------------------------------------------------------
// Problem dims (fixed for this dataset)
// ---------------------------------------------------------------------------
#define BDIM 256
#define DDIM 2048
#define HDIM 4096
#define MAX_STEPS 64

#define THREADS 256
#define NSTAGE 4

// ---------------------------------------------------------------------------
// Device scratch (no cudaMalloc allowed)
// ---------------------------------------------------------------------------
__device__ __half g_W1T[(size_t)HDIM * DDIM];   // [N=4096][K=2048] fp16
__device__ __half g_W2T[(size_t)DDIM * HDIM];   // [N=2048][K=4096] fp16
__device__ __half g_z_h[(size_t)BDIM * DDIM];
__device__ __half g_h1_h[(size_t)BDIM * HDIM];
__device__ float g_sched_t[MAX_STEPS];
__device__ float g_sched_h[MAX_STEPS];
__device__ int   g_nsteps;

// ---------------------------------------------------------------------------
// PTX helpers (compute_103-portable: cp.async, ldmatrix, mma.sync)
// ---------------------------------------------------------------------------
__device__ __forceinline__ uint32_t smem_to_u32(const void* p) {
    uint32_t a;
    asm("{ .reg .u64 t; cvta.to.shared.u64 t, %1; cvt.u32.u64 %0, t; }"
        : "=r"(a) : "l"(p));
    return a;
}

__device__ __forceinline__ void cp_async16(uint32_t dst, const void* src) {
    asm volatile("cp.async.cg.shared.global [%0], [%1], 16;"
                 :: "r"(dst), "l"(src));
}
#define CP_COMMIT() asm volatile("cp.async.commit_group;" ::: "memory")
#define CP_WAIT2()  asm volatile("cp.async.wait_group 2;" ::: "memory")

__device__ __forceinline__ void ldsm_x4(uint32_t& r0, uint32_t& r1,
                                        uint32_t& r2, uint32_t& r3,
                                        uint32_t addr) {
    asm volatile("ldmatrix.sync.aligned.m8n8.x4.shared.b16 {%0,%1,%2,%3}, [%4];"
                 : "=r"(r0), "=r"(r1), "=r"(r2), "=r"(r3) : "r"(addr));
}

__device__ __forceinline__ void mma_f16(float* c, const uint32_t* a,
                                        const uint32_t* b) {
    asm volatile(
        "mma.sync.aligned.m16n8k16.row.col.f32.f16.f16.f32 "
        "{%0,%1,%2,%3}, {%4,%5,%6,%7}, {%8,%9}, {%0,%1,%2,%3};"
        : "+f"(c[0]), "+f"(c[1]), "+f"(c[2]), "+f"(c[3])
        : "r"(a[0]), "r"(a[1]), "r"(a[2]), "r"(a[3]), "r"(b[0]), "r"(b[1]));
}

// Hardware tanh (MUFU.TANH, sm_75+): 1 instruction vs ~20 for tanhf.
__device__ __forceinline__ float tanh_approx(float x) {
    float y;
    asm("tanh.approx.f32 %0, %1;" : "=f"(y) : "f"(x));
    return y;
}

// ---------------------------------------------------------------------------
// Schedule: exact replica of the reference's host-side step scheduling
// ---------------------------------------------------------------------------
__global__ void schedule_kernel(const float* __restrict__ t, int T) {
    if (threadIdx.x != 0 || blockIdx.x != 0) return;
    int s = 0;
    for (int i = 0; i < T - 1; i++) {
        double t0 = (double)t[i];
        double t1 = (double)t[i + 1];
        double d  = fabs(t1 - t0);
        int n = (int)ceil(d / 0.05);
        if (n < 1) n = 1;
        float h = (float)((t1 - t0) / (double)n);
        float tc = t[i];
        for (int k = 0; k < n && s < MAX_STEPS; k++) {
            tc = tc + h;                 // t += h BEFORE f eval
            g_sched_t[s] = tc;
            g_sched_h[s] = h;
            s++;
        }
    }
    g_nsteps = s;
}

// ---------------------------------------------------------------------------
// Weight transpose + fp16 convert:  W[K][N] fp32 -> WT[N][K] fp16
// ---------------------------------------------------------------------------
__global__ void transpose_convert_kernel(const float* __restrict__ W,
                                         int K, int N, int which) {
    __shared__ float tile[32][33];
    const int k0 = blockIdx.y * 32;
    const int n0 = blockIdx.x * 32;
    const int tx = threadIdx.x % 32;
    const int ty = threadIdx.x / 32;

    #pragma unroll
    for (int i = 0; i < 32; i += 8)
        tile[ty + i][tx] = W[(size_t)(k0 + ty + i) * N + n0 + tx];
    __syncthreads();

    __half* T = which ? g_W2T : g_W1T;
    #pragma unroll
    for (int i = 0; i < 32; i += 8) {
        float v = tile[tx][ty + i];
        T[(size_t)(n0 + ty + i) * K + k0 + tx] = __float2half_rn(v);
    }
}

__global__ void zinit_kernel(const float* __restrict__ z0, float* __restrict__ z) {
    int i = blockIdx.x * blockDim.x + threadIdx.x;
    if (i >= BDIM * DDIM) return;
    float v = z0[i];
    z[i] = v;
    g_z_h[i] = __float2half_rn(v);
}

// ---------------------------------------------------------------------------
// Unified pipelined fp16 GEMM, 256 threads (8 warps), 4-stage cp.async.
// KCHUNK: K elements per SMEM stage (32 for gemmA, 64 for gemmB -> half the
// barriers with 512 MMA-issue cyc per barrier on both kernels).
//   MODE 0: h1 = tanh( z @ W1 + b1 + t*u )   A=g_z_h,  B=g_W1T, K=DDIM
//   MODE 1: z += h * ( h1 @ W2 + b2 )        A=g_h1_h, B=g_W2T, K=HDIM
// ---------------------------------------------------------------------------
template<int BMT, int BNT, int KCHUNK, int MODE>
__global__ void __launch_bounds__(THREADS, 2)
gemm_kernel(const float* __restrict__ bias, const float* __restrict__ uvec,
            float* __restrict__ z, int step)
{
    if (step >= g_nsteps) return;

    constexpr int WARPS_M = BMT / 32;
    constexpr int WARPS_N = 8 / WARPS_M;
    constexpr int WN = BNT / WARPS_N;      // warp tile N
    constexpr int NT = WN / 8;             // n8 frags per warp
    constexpr int KDIM = MODE ? HDIM : DDIM;
    constexpr int ROWB = 2 * KCHUNK + 16;  // row bytes + 16B pad (conflict-free)
    constexpr int RTOT = BMT + BNT;
    constexpr int ST_B = BMT * ROWB;
    constexpr int STAGE = RTOT * ROWB;
    constexpr int CPR = KCHUNK / 8;        // 16B chunks per row
    constexpr int NLOAD = RTOT * CPR / THREADS;
    constexpr int KK = KCHUNK / 16;        // k16 sub-steps per stage

    extern __shared__ char smem[];
    const uint32_t sbase = smem_to_u32(smem);
    const int tid = threadIdx.x;
    const int wid = tid >> 5, lane = tid & 31;
    const int warp_m = wid % WARPS_M;
    const int warp_n = wid / WARPS_M;
    const int m0 = blockIdx.y * BMT;
    const int n0 = blockIdx.x * BNT;

    const __half* __restrict__ A  = (MODE ? g_h1_h : g_z_h) + (size_t)m0 * KDIM;
    const __half* __restrict__ Bw = (MODE ? g_W2T  : g_W1T) + (size_t)n0 * KDIM;

    float acc[2][NT][4];
    #pragma unroll
    for (int mt = 0; mt < 2; mt++)
        #pragma unroll
        for (int nt = 0; nt < NT; nt++)
            #pragma unroll
            for (int q = 0; q < 4; q++) acc[mt][nt][q] = 0.0f;

    // --- stage loader ---
    auto load_stage = [&](uint32_t dstbase, int ko) {
        #pragma unroll
        for (int o = 0; o < NLOAD; o++) {
            int id = tid + THREADS * o;
            int row = id / CPR, ch = id % CPR;
            const __half* src = (row < BMT)
                ? A  + (size_t)row * KDIM + ko + ch * 8
                : Bw + (size_t)(row - BMT) * KDIM + ko + ch * 8;
            cp_async16(dstbase + row * ROWB + ch * 16, src);
        }
    };

    // --- per-stage compute ---
    auto compute_stage = [&](uint32_t st) {
        #pragma unroll
        for (int kk = 0; kk < KK; kk++) {
            uint32_t a[2][4];
            #pragma unroll
            for (int mt = 0; mt < 2; mt++) {
                uint32_t off = (uint32_t)((warp_m * 32 + mt * 16 + (lane & 15)) * ROWB
                                          + kk * 32 + ((lane >> 4) << 4));
                ldsm_x4(a[mt][0], a[mt][1], a[mt][2], a[mt][3], st + off);
            }
            uint32_t b[NT][2];
            #pragma unroll
            for (int pr = 0; pr < NT / 2; pr++) {
                uint32_t off = (uint32_t)(ST_B
                    + (warp_n * WN + pr * 16 + ((lane & 16) >> 1) + (lane & 7)) * ROWB
                    + kk * 32 + ((lane & 8) << 1));
                uint32_t r0, r1, r2, r3;
                ldsm_x4(r0, r1, r2, r3, st + off);
                b[2 * pr][0] = r0; b[2 * pr][1] = r1;
                b[2 * pr + 1][0] = r2; b[2 * pr + 1][1] = r3;
            }
            #pragma unroll
            for (int mt = 0; mt < 2; mt++)
                #pragma unroll
                for (int nt = 0; nt < NT; nt++)
                    mma_f16(acc[mt][nt], a[mt], b[nt]);
        }
    };

    // --- 4-stage pipeline ---
    const int nIter = KDIM / KCHUNK;
    load_stage(sbase + 0 * STAGE, 0);           CP_COMMIT();
    load_stage(sbase + 1 * STAGE, KCHUNK);      CP_COMMIT();
    load_stage(sbase + 2 * STAGE, 2 * KCHUNK);  CP_COMMIT();

    int stg = 0;
    for (int it = 0; it < nIter; it++) {
        CP_WAIT2();
        __syncthreads();
        compute_stage(sbase + stg * STAGE);
        int pf = it + 3;
        if (pf < nIter) {
            int ps = stg + 3; if (ps >= NSTAGE) ps -= NSTAGE;
            load_stage(sbase + ps * STAGE, pf * KCHUNK);
        }
        CP_COMMIT();
        stg++; if (stg == NSTAGE) stg = 0;
    }

    // --- epilogue ---
    const int grp = lane >> 2, qid = lane & 3;

    if (MODE == 0) {
        const float tb = g_sched_t[step];
        #pragma unroll
        for (int mt = 0; mt < 2; mt++) {
            #pragma unroll
            for (int nt = 0; nt < NT; nt++) {
                const int m = m0 + warp_m * 32 + mt * 16 + grp;
                const int n = n0 + warp_n * WN + nt * 8 + 2 * qid;
                const float bias0 = __ldg(&bias[n])     + tb * __ldg(&uvec[n]);
                const float bias1 = __ldg(&bias[n + 1]) + tb * __ldg(&uvec[n + 1]);
                #pragma unroll
                for (int half = 0; half < 2; half++) {
                    const int mm = m + 8 * half;
                    float y0 = tanh_approx(acc[mt][nt][2 * half + 0] + bias0);
                    float y1 = tanh_approx(acc[mt][nt][2 * half + 1] + bias1);
                    __half2 hv;
                    hv.x = __float2half_rn(y0);
                    hv.y = __float2half_rn(y1);
                    *(__half2*)&g_h1_h[(size_t)mm * HDIM + n] = hv;
                }
            }
        }
    } else {
        const float h = g_sched_h[step];
        #pragma unroll
        for (int mt = 0; mt < 2; mt++) {
            #pragma unroll
            for (int nt = 0; nt < NT; nt++) {
                const int m = m0 + warp_m * 32 + mt * 16 + grp;
                const int n = n0 + warp_n * WN + nt * 8 + 2 * qid;
                const float bias0 = __ldg(&bias[n]);
                const float bias1 = __ldg(&bias[n + 1]);
                #pragma unroll
                for (int half = 0; half < 2; half++) {
                    const int mm = m + 8 * half;
                    const size_t idx = (size_t)mm * DDIM + n;
                    float2 zv = *(float2*)&z[idx];
                    zv.x += h * (acc[mt][nt][2 * half + 0] + bias0);
                    zv.y += h * (acc[mt][nt][2 * half + 1] + bias1);
                    *(float2*)&z[idx] = zv;
                    __half2 hv;
                    hv.x = __float2half_rn(zv.x);
                    hv.y = __float2half_rn(zv.y);
                    *(__half2*)&g_z_h[idx] = hv;
                }
            }
        }
    }
}

// ---------------------------------------------------------------------------
// Launch
// ---------------------------------------------------------------------------
// gemmA: 128x64 tile, BK=32 (R12-identical): (128+64)*80*4 = 61440
#define SMEM_A ((128 + 64) * (2 * 32 + 16) * NSTAGE)
// gemmB: 64x64 tile, BK=64: (64+64)*144*4 = 73728
#define SMEM_B ((64 + 64) * (2 * 64 + 16) * NSTAGE)

extern "C" void kernel_launch(void* const* d_in, const int* in_sizes, int n_in,
                              void* d_out, int out_size)
{
    const float* z0 = (const float*)d_in[0];
    const float* t  = (const float*)d_in[1];
    const float* W1 = (const float*)d_in[2];
    const float* b1 = (const float*)d_in[3];
    const float* u  = (const float*)d_in[4];
    const float* W2 = (const float*)d_in[5];
    const float* b2 = (const float*)d_in[6];
    float* z = (float*)d_out;

    const int T = in_sizes[1];

    cudaFuncSetAttribute((const void*)gemm_kernel<128, 64, 32, 0>,
        cudaFuncAttributeMaxDynamicSharedMemorySize, SMEM_A);
    cudaFuncSetAttribute((const void*)gemm_kernel<64, 64, 64, 1>,
        cudaFuncAttributeMaxDynamicSharedMemorySize, SMEM_B);

    schedule_kernel<<<1, 32>>>(t, T);
    transpose_convert_kernel<<<dim3(HDIM / 32, DDIM / 32), 256>>>(W1, DDIM, HDIM, 0);
    transpose_convert_kernel<<<dim3(DDIM / 32, HDIM / 32), 256>>>(W2, HDIM, DDIM, 1);
    zinit_kernel<<<(BDIM * DDIM + 255) / 256, 256>>>(z0, z);

    int max_launch = 3 * (T - 1);
    if (max_launch > MAX_STEPS) max_launch = MAX_STEPS;

    const dim3 blk(THREADS);
    const dim3 gridA(HDIM / 64, BDIM / 128);   // 64 x 2 = 128 CTAs
    const dim3 gridB(DDIM / 64, BDIM / 64);    // 32 x 4 = 128 CTAs

    for (int s = 0; s < max_launch; s++) {
        gemm_kernel<128, 64, 32, 0><<<gridA, blk, SMEM_A>>>(b1, u, z, s);
        gemm_kernel<64, 64, 64, 1><<<gridB, blk, SMEM_B>>>(b2, nullptr, z, s);
    }
}

// round 16
// speedup vs baseline: 1.1471x; 1.0473x over previous
#include <cuda_runtime.h>
#include <cuda_fp16.h>
#include <math.h>
#include <stdint.h>

// ---------------------------------------------------------------------------
// Problem dims (fixed for this dataset)
// ---------------------------------------------------------------------------
#define BDIM 256
#define DDIM 2048
#define HDIM 4096
#define MAX_STEPS 64

#define THREADS 256
#define NSTAGE 4

// ---------------------------------------------------------------------------
// Device scratch (no cudaMalloc allowed)
// ---------------------------------------------------------------------------
__device__ __half g_W1T[(size_t)HDIM * DDIM];   // [N=4096][K=2048] fp16
__device__ __half g_W2T[(size_t)DDIM * HDIM];   // [N=2048][K=4096] fp16
__device__ __half g_z_h[(size_t)BDIM * DDIM];
__device__ __half g_h1_h[(size_t)BDIM * HDIM];
__device__ float g_sched_t[MAX_STEPS];
__device__ float g_sched_h[MAX_STEPS];
__device__ int   g_nsteps;

// ---------------------------------------------------------------------------
// PTX helpers (compute_103-portable: cp.async, ldmatrix, mma.sync)
// ---------------------------------------------------------------------------
__device__ __forceinline__ uint32_t smem_to_u32(const void* p) {
    uint32_t a;
    asm("{ .reg .u64 t; cvta.to.shared.u64 t, %1; cvt.u32.u64 %0, t; }"
        : "=r"(a) : "l"(p));
    return a;
}

__device__ __forceinline__ void cp_async16(uint32_t dst, const void* src) {
    asm volatile("cp.async.cg.shared.global [%0], [%1], 16;"
                 :: "r"(dst), "l"(src));
}
#define CP_COMMIT() asm volatile("cp.async.commit_group;" ::: "memory")
#define CP_WAIT2()  asm volatile("cp.async.wait_group 2;" ::: "memory")

__device__ __forceinline__ void ldsm_x4(uint32_t& r0, uint32_t& r1,
                                        uint32_t& r2, uint32_t& r3,
                                        uint32_t addr) {
    asm volatile("ldmatrix.sync.aligned.m8n8.x4.shared.b16 {%0,%1,%2,%3}, [%4];"
                 : "=r"(r0), "=r"(r1), "=r"(r2), "=r"(r3) : "r"(addr));
}

__device__ __forceinline__ void mma_f16(float* c, const uint32_t* a,
                                        const uint32_t* b) {
    asm volatile(
        "mma.sync.aligned.m16n8k16.row.col.f32.f16.f16.f32 "
        "{%0,%1,%2,%3}, {%4,%5,%6,%7}, {%8,%9}, {%0,%1,%2,%3};"
        : "+f"(c[0]), "+f"(c[1]), "+f"(c[2]), "+f"(c[3])
        : "r"(a[0]), "r"(a[1]), "r"(a[2]), "r"(a[3]), "r"(b[0]), "r"(b[1]));
}

// Hardware tanh (MUFU.TANH, sm_75+): 1 instruction vs ~20 for tanhf.
__device__ __forceinline__ float tanh_approx(float x) {
    float y;
    asm("tanh.approx.f32 %0, %1;" : "=f"(y) : "f"(x));
    return y;
}

// ---------------------------------------------------------------------------
// Schedule: exact replica of the reference's host-side step scheduling
// ---------------------------------------------------------------------------
__global__ void schedule_kernel(const float* __restrict__ t, int T) {
    if (threadIdx.x != 0 || blockIdx.x != 0) return;
    int s = 0;
    for (int i = 0; i < T - 1; i++) {
        double t0 = (double)t[i];
        double t1 = (double)t[i + 1];
        double d  = fabs(t1 - t0);
        int n = (int)ceil(d / 0.05);
        if (n < 1) n = 1;
        float h = (float)((t1 - t0) / (double)n);
        float tc = t[i];
        for (int k = 0; k < n && s < MAX_STEPS; k++) {
            tc = tc + h;                 // t += h BEFORE f eval
            g_sched_t[s] = tc;
            g_sched_h[s] = h;
            s++;
        }
    }
    g_nsteps = s;
}

// ---------------------------------------------------------------------------
// Weight transpose + fp16 convert:  W[K][N] fp32 -> WT[N][K] fp16
// ---------------------------------------------------------------------------
__global__ void transpose_convert_kernel(const float* __restrict__ W,
                                         int K, int N, int which) {
    __shared__ float tile[32][33];
    const int k0 = blockIdx.y * 32;
    const int n0 = blockIdx.x * 32;
    const int tx = threadIdx.x % 32;
    const int ty = threadIdx.x / 32;

    #pragma unroll
    for (int i = 0; i < 32; i += 8)
        tile[ty + i][tx] = W[(size_t)(k0 + ty + i) * N + n0 + tx];
    __syncthreads();

    __half* T = which ? g_W2T : g_W1T;
    #pragma unroll
    for (int i = 0; i < 32; i += 8) {
        float v = tile[tx][ty + i];
        T[(size_t)(n0 + ty + i) * K + k0 + tx] = __float2half_rn(v);
    }
}

__global__ void zinit_kernel(const float* __restrict__ z0, float* __restrict__ z) {
    int i = blockIdx.x * blockDim.x + threadIdx.x;
    if (i >= BDIM * DDIM) return;
    float v = z0[i];
    z[i] = v;
    g_z_h[i] = __float2half_rn(v);
}

// ---------------------------------------------------------------------------
// Unified pipelined fp16 GEMM, 256 threads (8 warps), 4-stage cp.async.
// KCHUNK=64 on both kernels: 1024 (gemmA) / 512 (gemmB) MMA-issue cycles per
// barrier -> minimal barrier exposure at 2 warps/SMSP.
//   MODE 0: h1 = tanh( z @ W1 + b1 + t*u )   A=g_z_h,  B=g_W1T, K=DDIM
//   MODE 1: z += h * ( h1 @ W2 + b2 )        A=g_h1_h, B=g_W2T, K=HDIM
// ---------------------------------------------------------------------------
template<int BMT, int BNT, int KCHUNK, int MODE>
__global__ void __launch_bounds__(THREADS, 2)
gemm_kernel(const float* __restrict__ bias, const float* __restrict__ uvec,
            float* __restrict__ z, int step)
{
    if (step >= g_nsteps) return;

    constexpr int WARPS_M = BMT / 32;
    constexpr int WARPS_N = 8 / WARPS_M;
    constexpr int WN = BNT / WARPS_N;      // warp tile N
    constexpr int NT = WN / 8;             // n8 frags per warp
    constexpr int KDIM = MODE ? HDIM : DDIM;
    constexpr int ROWB = 2 * KCHUNK + 16;  // row bytes + 16B pad (conflict-free)
    constexpr int RTOT = BMT + BNT;
    constexpr int ST_B = BMT * ROWB;
    constexpr int STAGE = RTOT * ROWB;
    constexpr int CPR = KCHUNK / 8;        // 16B chunks per row
    constexpr int NLOAD = RTOT * CPR / THREADS;
    constexpr int KK = KCHUNK / 16;        // k16 sub-steps per stage

    extern __shared__ char smem[];
    const uint32_t sbase = smem_to_u32(smem);
    const int tid = threadIdx.x;
    const int wid = tid >> 5, lane = tid & 31;
    const int warp_m = wid % WARPS_M;
    const int warp_n = wid / WARPS_M;
    const int m0 = blockIdx.y * BMT;
    const int n0 = blockIdx.x * BNT;

    const __half* __restrict__ A  = (MODE ? g_h1_h : g_z_h) + (size_t)m0 * KDIM;
    const __half* __restrict__ Bw = (MODE ? g_W2T  : g_W1T) + (size_t)n0 * KDIM;

    float acc[2][NT][4];
    #pragma unroll
    for (int mt = 0; mt < 2; mt++)
        #pragma unroll
        for (int nt = 0; nt < NT; nt++)
            #pragma unroll
            for (int q = 0; q < 4; q++) acc[mt][nt][q] = 0.0f;

    // --- stage loader ---
    auto load_stage = [&](uint32_t dstbase, int ko) {
        #pragma unroll
        for (int o = 0; o < NLOAD; o++) {
            int id = tid + THREADS * o;
            int row = id / CPR, ch = id % CPR;
            const __half* src = (row < BMT)
                ? A  + (size_t)row * KDIM + ko + ch * 8
                : Bw + (size_t)(row - BMT) * KDIM + ko + ch * 8;
            cp_async16(dstbase + row * ROWB + ch * 16, src);
        }
    };

    // --- per-stage compute ---
    auto compute_stage = [&](uint32_t st) {
        #pragma unroll
        for (int kk = 0; kk < KK; kk++) {
            uint32_t a[2][4];
            #pragma unroll
            for (int mt = 0; mt < 2; mt++) {
                uint32_t off = (uint32_t)((warp_m * 32 + mt * 16 + (lane & 15)) * ROWB
                                          + kk * 32 + ((lane >> 4) << 4));
                ldsm_x4(a[mt][0], a[mt][1], a[mt][2], a[mt][3], st + off);
            }
            uint32_t b[NT][2];
            #pragma unroll
            for (int pr = 0; pr < NT / 2; pr++) {
                uint32_t off = (uint32_t)(ST_B
                    + (warp_n * WN + pr * 16 + ((lane & 16) >> 1) + (lane & 7)) * ROWB
                    + kk * 32 + ((lane & 8) << 1));
                uint32_t r0, r1, r2, r3;
                ldsm_x4(r0, r1, r2, r3, st + off);
                b[2 * pr][0] = r0; b[2 * pr][1] = r1;
                b[2 * pr + 1][0] = r2; b[2 * pr + 1][1] = r3;
            }
            #pragma unroll
            for (int mt = 0; mt < 2; mt++)
                #pragma unroll
                for (int nt = 0; nt < NT; nt++)
                    mma_f16(acc[mt][nt], a[mt], b[nt]);
        }
    };

    // --- 4-stage pipeline ---
    const int nIter = KDIM / KCHUNK;
    load_stage(sbase + 0 * STAGE, 0);           CP_COMMIT();
    load_stage(sbase + 1 * STAGE, KCHUNK);      CP_COMMIT();
    load_stage(sbase + 2 * STAGE, 2 * KCHUNK);  CP_COMMIT();

    int stg = 0;
    for (int it = 0; it < nIter; it++) {
        CP_WAIT2();
        __syncthreads();
        compute_stage(sbase + stg * STAGE);
        int pf = it + 3;
        if (pf < nIter) {
            int ps = stg + 3; if (ps >= NSTAGE) ps -= NSTAGE;
            load_stage(sbase + ps * STAGE, pf * KCHUNK);
        }
        CP_COMMIT();
        stg++; if (stg == NSTAGE) stg = 0;
    }

    // --- epilogue ---
    const int grp = lane >> 2, qid = lane & 3;

    if (MODE == 0) {
        const float tb = g_sched_t[step];
        #pragma unroll
        for (int mt = 0; mt < 2; mt++) {
            #pragma unroll
            for (int nt = 0; nt < NT; nt++) {
                const int m = m0 + warp_m * 32 + mt * 16 + grp;
                const int n = n0 + warp_n * WN + nt * 8 + 2 * qid;
                const float bias0 = __ldg(&bias[n])     + tb * __ldg(&uvec[n]);
                const float bias1 = __ldg(&bias[n + 1]) + tb * __ldg(&uvec[n + 1]);
                #pragma unroll
                for (int half = 0; half < 2; half++) {
                    const int mm = m + 8 * half;
                    float y0 = tanh_approx(acc[mt][nt][2 * half + 0] + bias0);
                    float y1 = tanh_approx(acc[mt][nt][2 * half + 1] + bias1);
                    __half2 hv;
                    hv.x = __float2half_rn(y0);
                    hv.y = __float2half_rn(y1);
                    *(__half2*)&g_h1_h[(size_t)mm * HDIM + n] = hv;
                }
            }
        }
    } else {
        const float h = g_sched_h[step];
        #pragma unroll
        for (int mt = 0; mt < 2; mt++) {
            #pragma unroll
            for (int nt = 0; nt < NT; nt++) {
                const int m = m0 + warp_m * 32 + mt * 16 + grp;
                const int n = n0 + warp_n * WN + nt * 8 + 2 * qid;
                const float bias0 = __ldg(&bias[n]);
                const float bias1 = __ldg(&bias[n + 1]);
                #pragma unroll
                for (int half = 0; half < 2; half++) {
                    const int mm = m + 8 * half;
                    const size_t idx = (size_t)mm * DDIM + n;
                    float2 zv = *(float2*)&z[idx];
                    zv.x += h * (acc[mt][nt][2 * half + 0] + bias0);
                    zv.y += h * (acc[mt][nt][2 * half + 1] + bias1);
                    *(float2*)&z[idx] = zv;
                    __half2 hv;
                    hv.x = __float2half_rn(zv.x);
                    hv.y = __float2half_rn(zv.y);
                    *(__half2*)&g_z_h[idx] = hv;
                }
            }
        }
    }
}

// ---------------------------------------------------------------------------
// Launch
// ---------------------------------------------------------------------------
// gemmA: 128x64 tile, KCHUNK=64: (128+64)*144*4 = 110592
#define SMEM_A ((128 + 64) * (2 * 64 + 16) * NSTAGE)
// gemmB: 64x64 tile, KCHUNK=64: (64+64)*144*4 = 73728
#define SMEM_B ((64 + 64) * (2 * 64 + 16) * NSTAGE)

extern "C" void kernel_launch(void* const* d_in, const int* in_sizes, int n_in,
                              void* d_out, int out_size)
{
    const float* z0 = (const float*)d_in[0];
    const float* t  = (const float*)d_in[1];
    const float* W1 = (const float*)d_in[2];
    const float* b1 = (const float*)d_in[3];
    const float* u  = (const float*)d_in[4];
    const float* W2 = (const float*)d_in[5];
    const float* b2 = (const float*)d_in[6];
    float* z = (float*)d_out;

    const int T = in_sizes[1];

    cudaFuncSetAttribute((const void*)gemm_kernel<128, 64, 64, 0>,
        cudaFuncAttributeMaxDynamicSharedMemorySize, SMEM_A);
    cudaFuncSetAttribute((const void*)gemm_kernel<64, 64, 64, 1>,
        cudaFuncAttributeMaxDynamicSharedMemorySize, SMEM_B);

    schedule_kernel<<<1, 32>>>(t, T);
    transpose_convert_kernel<<<dim3(HDIM / 32, DDIM / 32), 256>>>(W1, DDIM, HDIM, 0);
    transpose_convert_kernel<<<dim3(DDIM / 32, HDIM / 32), 256>>>(W2, HDIM, DDIM, 1);
    zinit_kernel<<<(BDIM * DDIM + 255) / 256, 256>>>(z0, z);

    int max_launch = 3 * (T - 1);
    if (max_launch > MAX_STEPS) max_launch = MAX_STEPS;

    const dim3 blk(THREADS);
    const dim3 gridA(HDIM / 64, BDIM / 128);   // 64 x 2 = 128 CTAs
    const dim3 gridB(DDIM / 64, BDIM / 64);    // 32 x 4 = 128 CTAs

    for (int s = 0; s < max_launch; s++) {
        gemm_kernel<128, 64, 64, 0><<<gridA, blk, SMEM_A>>>(b1, u, z, s);
        gemm_kernel<64, 64, 64, 1><<<gridB, blk, SMEM_B>>>(b2, nullptr, z, s);
    }
}

// round 17
// speedup vs baseline: 1.1654x; 1.0160x over previous
#include <cuda_runtime.h>
#include <cuda_fp16.h>
#include <math.h>
#include <stdint.h>

// ---------------------------------------------------------------------------
// Problem dims (fixed for this dataset)
// ---------------------------------------------------------------------------
#define BDIM 256
#define DDIM 2048
#define HDIM 4096
#define MAX_STEPS 64

#define THREADS 256
#define NSTAGE 4

// ---------------------------------------------------------------------------
// Device scratch (no cudaMalloc allowed)
// ---------------------------------------------------------------------------
__device__ __half g_W1T[(size_t)HDIM * DDIM];   // [N=4096][K=2048] fp16
__device__ __half g_W2T[(size_t)DDIM * HDIM];   // [N=2048][K=4096] fp16
__device__ __half g_z_h[(size_t)BDIM * DDIM];
__device__ __half g_h1_h[(size_t)BDIM * HDIM];
__device__ float g_sched_t[MAX_STEPS];
__device__ float g_sched_h[MAX_STEPS];
__device__ int   g_nsteps;

// ---------------------------------------------------------------------------
// PTX helpers (compute_103-portable: cp.async, ldmatrix, mma.sync)
// ---------------------------------------------------------------------------
__device__ __forceinline__ uint32_t smem_to_u32(const void* p) {
    uint32_t a;
    asm("{ .reg .u64 t; cvta.to.shared.u64 t, %1; cvt.u32.u64 %0, t; }"
        : "=r"(a) : "l"(p));
    return a;
}

__device__ __forceinline__ void cp_async16(uint32_t dst, const void* src) {
    asm volatile("cp.async.cg.shared.global [%0], [%1], 16;"
                 :: "r"(dst), "l"(src));
}
#define CP_COMMIT() asm volatile("cp.async.commit_group;" ::: "memory")
#define CP_WAIT2()  asm volatile("cp.async.wait_group 2;" ::: "memory")

__device__ __forceinline__ void ldsm_x4(uint32_t& r0, uint32_t& r1,
                                        uint32_t& r2, uint32_t& r3,
                                        uint32_t addr) {
    asm volatile("ldmatrix.sync.aligned.m8n8.x4.shared.b16 {%0,%1,%2,%3}, [%4];"
                 : "=r"(r0), "=r"(r1), "=r"(r2), "=r"(r3) : "r"(addr));
}

__device__ __forceinline__ void mma_f16(float* c, const uint32_t* a,
                                        const uint32_t* b) {
    asm volatile(
        "mma.sync.aligned.m16n8k16.row.col.f32.f16.f16.f32 "
        "{%0,%1,%2,%3}, {%4,%5,%6,%7}, {%8,%9}, {%0,%1,%2,%3};"
        : "+f"(c[0]), "+f"(c[1]), "+f"(c[2]), "+f"(c[3])
        : "r"(a[0]), "r"(a[1]), "r"(a[2]), "r"(a[3]), "r"(b[0]), "r"(b[1]));
}

// Hardware tanh (MUFU.TANH, sm_75+): 1 instruction vs ~20 for tanhf.
__device__ __forceinline__ float tanh_approx(float x) {
    float y;
    asm("tanh.approx.f32 %0, %1;" : "=f"(y) : "f"(x));
    return y;
}

// ---------------------------------------------------------------------------
// Schedule: exact replica of the reference's host-side step scheduling
// ---------------------------------------------------------------------------
__global__ void schedule_kernel(const float* __restrict__ t, int T) {
    if (threadIdx.x != 0 || blockIdx.x != 0) return;
    int s = 0;
    for (int i = 0; i < T - 1; i++) {
        double t0 = (double)t[i];
        double t1 = (double)t[i + 1];
        double d  = fabs(t1 - t0);
        int n = (int)ceil(d / 0.05);
        if (n < 1) n = 1;
        float h = (float)((t1 - t0) / (double)n);
        float tc = t[i];
        for (int k = 0; k < n && s < MAX_STEPS; k++) {
            tc = tc + h;                 // t += h BEFORE f eval
            g_sched_t[s] = tc;
            g_sched_h[s] = h;
            s++;
        }
    }
    g_nsteps = s;
}

// ---------------------------------------------------------------------------
// Weight transpose + fp16 convert:  W[K][N] fp32 -> WT[N][K] fp16
// ---------------------------------------------------------------------------
__global__ void transpose_convert_kernel(const float* __restrict__ W,
                                         int K, int N, int which) {
    __shared__ float tile[32][33];
    const int k0 = blockIdx.y * 32;
    const int n0 = blockIdx.x * 32;
    const int tx = threadIdx.x % 32;
    const int ty = threadIdx.x / 32;

    #pragma unroll
    for (int i = 0; i < 32; i += 8)
        tile[ty + i][tx] = W[(size_t)(k0 + ty + i) * N + n0 + tx];
    __syncthreads();

    __half* T = which ? g_W2T : g_W1T;
    #pragma unroll
    for (int i = 0; i < 32; i += 8) {
        float v = tile[tx][ty + i];
        T[(size_t)(n0 + ty + i) * K + k0 + tx] = __float2half_rn(v);
    }
}

__global__ void zinit_kernel(const float* __restrict__ z0, float* __restrict__ z) {
    int i = blockIdx.x * blockDim.x + threadIdx.x;
    if (i >= BDIM * DDIM) return;
    float v = z0[i];
    z[i] = v;
    g_z_h[i] = __float2half_rn(v);
}

// ---------------------------------------------------------------------------
// Unified pipelined fp16 GEMM, 256 threads (8 warps), 4-stage cp.async.
// KCHUNK=128 on both kernels: 2048 (gemmA) / 1024 (gemmB) MMA-issue cycles
// per barrier -> minimal barrier exposure at 2 warps/SMSP.
//   MODE 0: h1 = tanh( z @ W1 + b1 + t*u )   A=g_z_h,  B=g_W1T, K=DDIM
//   MODE 1: z += h * ( h1 @ W2 + b2 )        A=g_h1_h, B=g_W2T, K=HDIM
// ---------------------------------------------------------------------------
template<int BMT, int BNT, int KCHUNK, int MODE>
__global__ void __launch_bounds__(THREADS, 1)
gemm_kernel(const float* __restrict__ bias, const float* __restrict__ uvec,
            float* __restrict__ z, int step)
{
    if (step >= g_nsteps) return;

    constexpr int WARPS_M = BMT / 32;
    constexpr int WARPS_N = 8 / WARPS_M;
    constexpr int WN = BNT / WARPS_N;      // warp tile N
    constexpr int NT = WN / 8;             // n8 frags per warp
    constexpr int KDIM = MODE ? HDIM : DDIM;
    constexpr int ROWB = 2 * KCHUNK + 16;  // row bytes + 16B pad (conflict-free)
    constexpr int RTOT = BMT + BNT;
    constexpr int ST_B = BMT * ROWB;
    constexpr int STAGE = RTOT * ROWB;
    constexpr int CPR = KCHUNK / 8;        // 16B chunks per row
    constexpr int NLOAD = RTOT * CPR / THREADS;
    constexpr int KK = KCHUNK / 16;        // k16 sub-steps per stage

    extern __shared__ char smem[];
    const uint32_t sbase = smem_to_u32(smem);
    const int tid = threadIdx.x;
    const int wid = tid >> 5, lane = tid & 31;
    const int warp_m = wid % WARPS_M;
    const int warp_n = wid / WARPS_M;
    const int m0 = blockIdx.y * BMT;
    const int n0 = blockIdx.x * BNT;

    const __half* __restrict__ A  = (MODE ? g_h1_h : g_z_h) + (size_t)m0 * KDIM;
    const __half* __restrict__ Bw = (MODE ? g_W2T  : g_W1T) + (size_t)n0 * KDIM;

    float acc[2][NT][4];
    #pragma unroll
    for (int mt = 0; mt < 2; mt++)
        #pragma unroll
        for (int nt = 0; nt < NT; nt++)
            #pragma unroll
            for (int q = 0; q < 4; q++) acc[mt][nt][q] = 0.0f;

    // --- stage loader ---
    auto load_stage = [&](uint32_t dstbase, int ko) {
        #pragma unroll
        for (int o = 0; o < NLOAD; o++) {
            int id = tid + THREADS * o;
            int row = id / CPR, ch = id % CPR;
            const __half* src = (row < BMT)
                ? A  + (size_t)row * KDIM + ko + ch * 8
                : Bw + (size_t)(row - BMT) * KDIM + ko + ch * 8;
            cp_async16(dstbase + row * ROWB + ch * 16, src);
        }
    };

    // --- per-stage compute ---
    auto compute_stage = [&](uint32_t st) {
        #pragma unroll
        for (int kk = 0; kk < KK; kk++) {
            uint32_t a[2][4];
            #pragma unroll
            for (int mt = 0; mt < 2; mt++) {
                uint32_t off = (uint32_t)((warp_m * 32 + mt * 16 + (lane & 15)) * ROWB
                                          + kk * 32 + ((lane >> 4) << 4));
                ldsm_x4(a[mt][0], a[mt][1], a[mt][2], a[mt][3], st + off);
            }
            uint32_t b[NT][2];
            #pragma unroll
            for (int pr = 0; pr < NT / 2; pr++) {
                uint32_t off = (uint32_t)(ST_B
                    + (warp_n * WN + pr * 16 + ((lane & 16) >> 1) + (lane & 7)) * ROWB
                    + kk * 32 + ((lane & 8) << 1));
                uint32_t r0, r1, r2, r3;
                ldsm_x4(r0, r1, r2, r3, st + off);
                b[2 * pr][0] = r0; b[2 * pr][1] = r1;
                b[2 * pr + 1][0] = r2; b[2 * pr + 1][1] = r3;
            }
            #pragma unroll
            for (int mt = 0; mt < 2; mt++)
                #pragma unroll
                for (int nt = 0; nt < NT; nt++)
                    mma_f16(acc[mt][nt], a[mt], b[nt]);
        }
    };

    // --- 4-stage pipeline ---
    const int nIter = KDIM / KCHUNK;
    load_stage(sbase + 0 * STAGE, 0);           CP_COMMIT();
    load_stage(sbase + 1 * STAGE, KCHUNK);      CP_COMMIT();
    load_stage(sbase + 2 * STAGE, 2 * KCHUNK);  CP_COMMIT();

    int stg = 0;
    for (int it = 0; it < nIter; it++) {
        CP_WAIT2();
        __syncthreads();
        compute_stage(sbase + stg * STAGE);
        int pf = it + 3;
        if (pf < nIter) {
            int ps = stg + 3; if (ps >= NSTAGE) ps -= NSTAGE;
            load_stage(sbase + ps * STAGE, pf * KCHUNK);
        }
        CP_COMMIT();
        stg++; if (stg == NSTAGE) stg = 0;
    }

    // --- epilogue ---
    const int grp = lane >> 2, qid = lane & 3;

    if (MODE == 0) {
        const float tb = g_sched_t[step];
        #pragma unroll
        for (int mt = 0; mt < 2; mt++) {
            #pragma unroll
            for (int nt = 0; nt < NT; nt++) {
                const int m = m0 + warp_m * 32 + mt * 16 + grp;
                const int n = n0 + warp_n * WN + nt * 8 + 2 * qid;
                const float bias0 = __ldg(&bias[n])     + tb * __ldg(&uvec[n]);
                const float bias1 = __ldg(&bias[n + 1]) + tb * __ldg(&uvec[n + 1]);
                #pragma unroll
                for (int half = 0; half < 2; half++) {
                    const int mm = m + 8 * half;
                    float y0 = tanh_approx(acc[mt][nt][2 * half + 0] + bias0);
                    float y1 = tanh_approx(acc[mt][nt][2 * half + 1] + bias1);
                    __half2 hv;
                    hv.x = __float2half_rn(y0);
                    hv.y = __float2half_rn(y1);
                    *(__half2*)&g_h1_h[(size_t)mm * HDIM + n] = hv;
                }
            }
        }
    } else {
        const float h = g_sched_h[step];
        #pragma unroll
        for (int mt = 0; mt < 2; mt++) {
            #pragma unroll
            for (int nt = 0; nt < NT; nt++) {
                const int m = m0 + warp_m * 32 + mt * 16 + grp;
                const int n = n0 + warp_n * WN + nt * 8 + 2 * qid;
                const float bias0 = __ldg(&bias[n]);
                const float bias1 = __ldg(&bias[n + 1]);
                #pragma unroll
                for (int half = 0; half < 2; half++) {
                    const int mm = m + 8 * half;
                    const size_t idx = (size_t)mm * DDIM + n;
                    float2 zv = *(float2*)&z[idx];
                    zv.x += h * (acc[mt][nt][2 * half + 0] + bias0);
                    zv.y += h * (acc[mt][nt][2 * half + 1] + bias1);
                    *(float2*)&z[idx] = zv;
                    __half2 hv;
                    hv.x = __float2half_rn(zv.x);
                    hv.y = __float2half_rn(zv.y);
                    *(__half2*)&g_z_h[idx] = hv;
                }
            }
        }
    }
}

// ---------------------------------------------------------------------------
// Launch
// ---------------------------------------------------------------------------
// gemmA: 128x64 tile, KCHUNK=128: (128+64)*272*4 = 208896
#define SMEM_A ((128 + 64) * (2 * 128 + 16) * NSTAGE)
// gemmB: 64x64 tile, KCHUNK=128: (64+64)*272*4 = 139264
#define SMEM_B ((64 + 64) * (2 * 128 + 16) * NSTAGE)

extern "C" void kernel_launch(void* const* d_in, const int* in_sizes, int n_in,
                              void* d_out, int out_size)
{
    const float* z0 = (const float*)d_in[0];
    const float* t  = (const float*)d_in[1];
    const float* W1 = (const float*)d_in[2];
    const float* b1 = (const float*)d_in[3];
    const float* u  = (const float*)d_in[4];
    const float* W2 = (const float*)d_in[5];
    const float* b2 = (const float*)d_in[6];
    float* z = (float*)d_out;

    const int T = in_sizes[1];

    cudaFuncSetAttribute((const void*)gemm_kernel<128, 64, 128, 0>,
        cudaFuncAttributeMaxDynamicSharedMemorySize, SMEM_A);
    cudaFuncSetAttribute((const void*)gemm_kernel<64, 64, 128, 1>,
        cudaFuncAttributeMaxDynamicSharedMemorySize, SMEM_B);

    schedule_kernel<<<1, 32>>>(t, T);
    transpose_convert_kernel<<<dim3(HDIM / 32, DDIM / 32), 256>>>(W1, DDIM, HDIM, 0);
    transpose_convert_kernel<<<dim3(DDIM / 32, HDIM / 32), 256>>>(W2, HDIM, DDIM, 1);
    zinit_kernel<<<(BDIM * DDIM + 255) / 256, 256>>>(z0, z);

    int max_launch = 3 * (T - 1);
    if (max_launch > MAX_STEPS) max_launch = MAX_STEPS;

    const dim3 blk(THREADS);
    const dim3 gridA(HDIM / 64, BDIM / 128);   // 64 x 2 = 128 CTAs
    const dim3 gridB(DDIM / 64, BDIM / 64);    // 32 x 4 = 128 CTAs

    for (int s = 0; s < max_launch; s++) {
        gemm_kernel<128, 64, 128, 0><<<gridA, blk, SMEM_A>>>(b1, u, z, s);
        gemm_kernel<64, 64, 128, 1><<<gridB, blk, SMEM_B>>>(b2, nullptr, z, s);
    }
}